// round 5
// baseline (speedup 1.0000x reference)
#include <cuda_runtime.h>

// GradientLayer: 4->256->256->256->256->2 tanh MLP, forward jet propagation of
// (value, d/dx0..d/dx3, d2/dx0^2..d2/dx2^2) per neuron (8 channels), packed as
// f32x2 pairs to hit the doubled fp32 FFMA2 rate on sm_103a.

#define HDIM 256
#define SAMP 8      // samples per block (== warps per block)
#define DIN  4

__device__ __forceinline__ unsigned long long ffma2(unsigned long long a,
                                                    unsigned long long b,
                                                    unsigned long long c) {
    unsigned long long d;
    asm("fma.rn.f32x2 %0, %1, %2, %3;" : "=l"(d) : "l"(a), "l"(b), "l"(c));
    return d;
}
__device__ __forceinline__ unsigned long long pack2(float lo, float hi) {
    unsigned long long r;
    asm("mov.b64 %0, {%1, %2};" : "=l"(r) : "f"(lo), "f"(hi));
    return r;
}
__device__ __forceinline__ void unpack2(unsigned long long v, float& a, float& b) {
    asm("mov.b64 {%0, %1}, %2;" : "=f"(a), "=f"(b) : "l"(v));
}

__global__ void __launch_bounds__(256, 2)
mlp_jet_kernel(const float* __restrict__ x,
               const float* __restrict__ W0, const float* __restrict__ b0,
               const float* __restrict__ W1, const float* __restrict__ b1,
               const float* __restrict__ W2, const float* __restrict__ b2,
               const float* __restrict__ W3, const float* __restrict__ b3,
               const float* __restrict__ Wo, const float* __restrict__ bo,
               float* __restrict__ out, int B)
{
    extern __shared__ float sm[];          // [SAMP][HDIM][8] = 64 KB
    __shared__ float xs[SAMP * DIN];

    const int j  = threadIdx.x;            // neuron index, 0..255
    const int s0 = blockIdx.x * SAMP;

    // stage this block's inputs
    if (j < SAMP * DIN) {
        int ss = j / DIN, kk = j % DIN;
        int gs = s0 + ss;
        xs[j] = (gs < B) ? x[gs * DIN + kk] : 0.0f;
    }

    // ---- layer 0: 4 -> 256 (input jets: g_i = e_i, h = 0) ----
    const float w00 = W0[0 * HDIM + j];
    const float w01 = W0[1 * HDIM + j];
    const float w02 = W0[2 * HDIM + j];
    const float w03 = W0[3 * HDIM + j];
    const float bb0 = b0[j];
    __syncthreads();

    #pragma unroll
    for (int s = 0; s < SAMP; s++) {
        float u = bb0 + xs[s * 4 + 0] * w00 + xs[s * 4 + 1] * w01
                      + xs[s * 4 + 2] * w02 + xs[s * 4 + 3] * w03;
        float v = tanhf(u);
        float d = 1.0f - v * v;
        float m = -2.0f * v * d;
        float4* p = (float4*)&sm[(s * HDIM + j) * 8];
        p[0] = make_float4(v, d * w00, d * w01, d * w02);
        p[1] = make_float4(d * w03, m * w00 * w00, m * w01 * w01, m * w02 * w02);
    }
    __syncthreads();

    // ---- hidden layers 1..3: 256 -> 256 jet GEMM + tanh jet ----
    const float* Wlist[3] = { W1, W2, W3 };
    const float* blist[3] = { b1, b2, b3 };
    #pragma unroll
    for (int layer = 0; layer < 3; layer++) {
        const float* __restrict__ Wj = Wlist[layer] + j;
        unsigned long long acc[SAMP][4];
        #pragma unroll
        for (int s = 0; s < SAMP; s++) {
            acc[s][0] = 0ull; acc[s][1] = 0ull; acc[s][2] = 0ull; acc[s][3] = 0ull;
        }

        #pragma unroll 4
        for (int k = 0; k < HDIM; k++) {
            float w = __ldg(Wj + k * HDIM);
            unsigned long long ww = pack2(w, w);
            #pragma unroll
            for (int s = 0; s < SAMP; s++) {
                const ulonglong2* sp = (const ulonglong2*)&sm[(s * HDIM + k) * 8];
                ulonglong2 q0 = sp[0];   // (v,g0),(g1,g2)
                ulonglong2 q1 = sp[1];   // (g3,h0),(h1,h2)
                acc[s][0] = ffma2(q0.x, ww, acc[s][0]);
                acc[s][1] = ffma2(q0.y, ww, acc[s][1]);
                acc[s][2] = ffma2(q1.x, ww, acc[s][2]);
                acc[s][3] = ffma2(q1.y, ww, acc[s][3]);
            }
        }

        const float bl = blist[layer][j];
        __syncthreads();   // all reads of current state done before overwrite

        #pragma unroll
        for (int s = 0; s < SAMP; s++) {
            float uv, g0, g1, g2, g3, h0, h1, h2;
            unpack2(acc[s][0], uv, g0);
            unpack2(acc[s][1], g1, g2);
            unpack2(acc[s][2], g3, h0);
            unpack2(acc[s][3], h1, h2);
            uv += bl;
            float v = tanhf(uv);
            float d = 1.0f - v * v;
            float m = -2.0f * v * d;
            float4* p = (float4*)&sm[(s * HDIM + j) * 8];
            p[0] = make_float4(v, d * g0, d * g1, d * g2);
            p[1] = make_float4(d * g3,
                               d * h0 + m * g0 * g0,
                               d * h1 + m * g1 * g1,
                               d * h2 + m * g2 * g2);
        }
        __syncthreads();
    }

    // ---- output layer 256 -> 2 + divergence epilogue: one warp per sample ----
    const int warp = j >> 5;
    const int lane = j & 31;
    const int gs   = s0 + warp;

    float p0[8], p1[8];
    #pragma unroll
    for (int c = 0; c < 8; c++) { p0[c] = 0.0f; p1[c] = 0.0f; }

    #pragma unroll
    for (int t = 0; t < 8; t++) {
        int jj = lane + t * 32;
        float wo0 = Wo[jj * 2 + 0];
        float wo1 = Wo[jj * 2 + 1];
        const float* st = &sm[(warp * HDIM + jj) * 8];
        #pragma unroll
        for (int c = 0; c < 8; c++) {
            float sv = st[c];
            p0[c] = fmaf(sv, wo0, p0[c]);
            p1[c] = fmaf(sv, wo1, p1[c]);
        }
    }
    #pragma unroll
    for (int off = 16; off > 0; off >>= 1) {
        #pragma unroll
        for (int c = 0; c < 8; c++) {
            p0[c] += __shfl_xor_sync(0xffffffffu, p0[c], off);
            p1[c] += __shfl_xor_sync(0xffffffffu, p1[c], off);
        }
    }

    if (lane == 0 && gs < B) {
        float c   = p0[0] + bo[0];
        float Fi  = p1[0] + bo[1];
        float ct  = p0[4];                      // dc/dx3 (TDIM=3)
        float cg0 = p0[1], cg1 = p0[2], cg2 = p0[3];
        float fg0 = p1[1], fg1 = p1[2], fg2 = p1[3];
        float clap = p0[5] + p0[6] + p0[7];     // trace Hc[:3,:3]
        float flap = p1[5] + p1[6] + p1[7];     // trace HFi[:3,:3]
        // j_div = -D_C*clap - K_C*(cg.fg + c*flap) + V_C*sum(cg)
        float jdiv = -clap
                   - (cg0 * fg0 + cg1 * fg1 + cg2 * fg2 + c * flap)
                   + 0.1f * (cg0 + cg1 + cg2);

        out[gs]                   = c;
        out[B + gs]               = ct;
        out[2 * B + gs * 3 + 0]   = cg0;
        out[2 * B + gs * 3 + 1]   = cg1;
        out[2 * B + gs * 3 + 2]   = cg2;
        out[5 * B + gs]           = Fi;
        out[6 * B + gs * 3 + 0]   = fg0;
        out[6 * B + gs * 3 + 1]   = fg1;
        out[6 * B + gs * 3 + 2]   = fg2;
        out[9 * B + gs]           = flap;
        out[10 * B + gs]          = jdiv;
    }
}

extern "C" void kernel_launch(void* const* d_in, const int* in_sizes, int n_in,
                              void* d_out, int out_size)
{
    const float* x  = (const float*)d_in[0];
    const float* W0 = (const float*)d_in[1];
    const float* b0 = (const float*)d_in[2];
    const float* W1 = (const float*)d_in[3];
    const float* b1 = (const float*)d_in[4];
    const float* W2 = (const float*)d_in[5];
    const float* b2 = (const float*)d_in[6];
    const float* W3 = (const float*)d_in[7];
    const float* b3 = (const float*)d_in[8];
    const float* Wo = (const float*)d_in[9];
    const float* bo = (const float*)d_in[10];
    float* out = (float*)d_out;

    const int B = in_sizes[0] / DIN;
    const int smem = SAMP * HDIM * 8 * (int)sizeof(float);  // 64 KB

    cudaFuncSetAttribute(mlp_jet_kernel,
                         cudaFuncAttributeMaxDynamicSharedMemorySize, smem);

    dim3 grid((B + SAMP - 1) / SAMP);
    mlp_jet_kernel<<<grid, 256, smem>>>(x, W0, b0, W1, b1, W2, b2, W3, b3,
                                        Wo, bo, out, B);
}

// round 6
// speedup vs baseline: 1.6647x; 1.6647x over previous
#include <cuda_runtime.h>

// GradientLayer: 4->256->256->256->256->2 tanh MLP, forward jet propagation of
// (value, d/dx0..d/dx3, d2/dx0^2..d2/dx2^2) = 8 channels per neuron.
// Register-tiled jet-GEMM: thread (m = sample, n = j-group) owns an
// 8ch x 8j accumulator tile of f32x2 pairs; A-frag (state) and B-frag
// (smem-staged W tile) are reused 8x per load, flipping the bottleneck
// from the smem pipe (95% in R4) to the FFMA2 pipe.

#define HDIM 256
#define SAMP 8
#define DIN  4
#define KT   32                    // k rows staged per W tile
#define SROW 2052                  // state floats per sample: 256*8 + 4 pad (bank spread)

__device__ __forceinline__ unsigned long long ffma2(unsigned long long a,
                                                    unsigned long long b,
                                                    unsigned long long c) {
    unsigned long long d;
    asm("fma.rn.f32x2 %0, %1, %2, %3;" : "=l"(d) : "l"(a), "l"(b), "l"(c));
    return d;
}
__device__ __forceinline__ unsigned long long pack2(float lo, float hi) {
    unsigned long long r;
    asm("mov.b64 %0, {%1, %2};" : "=l"(r) : "f"(lo), "f"(hi));
    return r;
}
__device__ __forceinline__ void unpack2(unsigned long long v, float& a, float& b) {
    asm("mov.b64 {%0, %1}, %2;" : "=f"(a), "=f"(b) : "l"(v));
}

__global__ void __launch_bounds__(256, 2)
mlp_jet_kernel(const float* __restrict__ x,
               const float* __restrict__ W0, const float* __restrict__ b0,
               const float* __restrict__ W1, const float* __restrict__ b1,
               const float* __restrict__ W2, const float* __restrict__ b2,
               const float* __restrict__ W3, const float* __restrict__ b3,
               const float* __restrict__ Wo, const float* __restrict__ bo,
               float* __restrict__ out, int B)
{
    extern __shared__ float smem[];
    float* wsm = smem;                    // KT x 256 staged W tile (32 KB)
    float* st  = smem + KT * HDIM;        // state: SAMP x SROW (~64 KB, padded)
    __shared__ float xs[SAMP * DIN];

    const int tid = threadIdx.x;
    const int m   = tid & 7;              // sample within block
    const int n   = tid >> 3;             // j-group: this thread owns j0..j0+7
    const int j0  = n * 8;
    const int s0  = blockIdx.x * SAMP;

    if (tid < SAMP * DIN) {
        int ss = tid / DIN, kk = tid % DIN;
        int gs = s0 + ss;
        xs[tid] = (gs < B) ? x[gs * DIN + kk] : 0.0f;
    }
    __syncthreads();

    // ---- layer 0: 4 -> 256. Input jets: g_i = e_i, h = 0. ----
    {
        float x0 = xs[m * 4 + 0], x1 = xs[m * 4 + 1];
        float x2 = xs[m * 4 + 2], x3 = xs[m * 4 + 3];
        float4 w0a = *(const float4*)(W0 + 0 * HDIM + j0);
        float4 w0b = *(const float4*)(W0 + 0 * HDIM + j0 + 4);
        float4 w1a = *(const float4*)(W0 + 1 * HDIM + j0);
        float4 w1b = *(const float4*)(W0 + 1 * HDIM + j0 + 4);
        float4 w2a = *(const float4*)(W0 + 2 * HDIM + j0);
        float4 w2b = *(const float4*)(W0 + 2 * HDIM + j0 + 4);
        float4 w3a = *(const float4*)(W0 + 3 * HDIM + j0);
        float4 w3b = *(const float4*)(W0 + 3 * HDIM + j0 + 4);
        float4 ba  = *(const float4*)(b0 + j0);
        float4 bb  = *(const float4*)(b0 + j0 + 4);
        const float* wa0 = &w0a.x; const float* wb0 = &w0b.x;
        const float* wa1 = &w1a.x; const float* wb1 = &w1b.x;
        const float* wa2 = &w2a.x; const float* wb2 = &w2b.x;
        const float* wa3 = &w3a.x; const float* wb3 = &w3b.x;
        const float* bap = &ba.x;  const float* bbp = &bb.x;
        #pragma unroll
        for (int jj = 0; jj < 8; jj++) {
            float c0 = (jj < 4) ? wa0[jj & 3] : wb0[jj & 3];
            float c1 = (jj < 4) ? wa1[jj & 3] : wb1[jj & 3];
            float c2 = (jj < 4) ? wa2[jj & 3] : wb2[jj & 3];
            float c3 = (jj < 4) ? wa3[jj & 3] : wb3[jj & 3];
            float bl = (jj < 4) ? bap[jj & 3] : bbp[jj & 3];
            float u = bl + x0 * c0 + x1 * c1 + x2 * c2 + x3 * c3;
            float v = tanhf(u);
            float d = 1.0f - v * v;
            float mm = -2.0f * v * d;
            float4* p = (float4*)&st[m * SROW + (j0 + jj) * 8];
            p[0] = make_float4(v, d * c0, d * c1, d * c2);
            p[1] = make_float4(d * c3, mm * c0 * c0, mm * c1 * c1, mm * c2 * c2);
        }
    }

    // ---- hidden layers 1..3: 256 -> 256 register-tiled jet GEMM ----
    const float* Wlist[3] = { W1, W2, W3 };
    const float* blist[3] = { b1, b2, b3 };
    #pragma unroll 1
    for (int layer = 0; layer < 3; layer++) {
        const float* __restrict__ Wl = Wlist[layer];

        unsigned long long acc0[8], acc1[8], acc2[8], acc3[8];
        #pragma unroll
        for (int jj = 0; jj < 8; jj++) {
            acc0[jj] = 0ull; acc1[jj] = 0ull; acc2[jj] = 0ull; acc3[jj] = 0ull;
        }

        #pragma unroll 1
        for (int t = 0; t < HDIM / KT; t++) {
            __syncthreads();   // prior tile fully consumed / prior state written
            // stage W rows [t*KT, t*KT+KT) : KT*256 floats, coalesced float4
            {
                const float4* src = (const float4*)(Wl + t * KT * HDIM);
                float4* dst = (float4*)wsm;
                #pragma unroll
                for (int i = 0; i < (KT * HDIM / 4) / 256; i++)
                    dst[tid + i * 256] = src[tid + i * 256];
            }
            __syncthreads();

            const float* abase = st + m * SROW + t * KT * 8;
            #pragma unroll 8
            for (int kk = 0; kk < KT; kk++) {
                const ulonglong2* ap = (const ulonglong2*)(abase + kk * 8);
                ulonglong2 a01 = ap[0];   // (v,g0) | (g1,g2)
                ulonglong2 a23 = ap[1];   // (g3,h0) | (h1,h2)
                const float* wr = wsm + kk * HDIM + j0;
                float4 wlo = *(const float4*)wr;
                float4 whi = *(const float4*)(wr + 4);
                unsigned long long ww[8];
                ww[0] = pack2(wlo.x, wlo.x); ww[1] = pack2(wlo.y, wlo.y);
                ww[2] = pack2(wlo.z, wlo.z); ww[3] = pack2(wlo.w, wlo.w);
                ww[4] = pack2(whi.x, whi.x); ww[5] = pack2(whi.y, whi.y);
                ww[6] = pack2(whi.z, whi.z); ww[7] = pack2(whi.w, whi.w);
                #pragma unroll
                for (int jj = 0; jj < 8; jj++) {
                    acc0[jj] = ffma2(a01.x, ww[jj], acc0[jj]);
                    acc1[jj] = ffma2(a01.y, ww[jj], acc1[jj]);
                    acc2[jj] = ffma2(a23.x, ww[jj], acc2[jj]);
                    acc3[jj] = ffma2(a23.y, ww[jj], acc3[jj]);
                }
            }
        }

        float4 bla = *(const float4*)(blist[layer] + j0);
        float4 blb = *(const float4*)(blist[layer] + j0 + 4);
        const float* blap = &bla.x; const float* blbp = &blb.x;

        __syncthreads();   // all reads of current state done before overwrite

        #pragma unroll
        for (int jj = 0; jj < 8; jj++) {
            float uv, g0, g1, g2, g3, h0, h1, h2;
            unpack2(acc0[jj], uv, g0);
            unpack2(acc1[jj], g1, g2);
            unpack2(acc2[jj], g3, h0);
            unpack2(acc3[jj], h1, h2);
            uv += (jj < 4) ? blap[jj & 3] : blbp[jj & 3];
            float v = tanhf(uv);
            float d = 1.0f - v * v;
            float mm = -2.0f * v * d;
            float4* p = (float4*)&st[m * SROW + (j0 + jj) * 8];
            p[0] = make_float4(v, d * g0, d * g1, d * g2);
            p[1] = make_float4(d * g3,
                               d * h0 + mm * g0 * g0,
                               d * h1 + mm * g1 * g1,
                               d * h2 + mm * g2 * g2);
        }
    }
    __syncthreads();

    // ---- output layer 256 -> 2 + divergence epilogue: one warp per sample ----
    const int warp = tid >> 5;
    const int lane = tid & 31;
    const int gs   = s0 + warp;

    float p0[8], p1[8];
    #pragma unroll
    for (int c = 0; c < 8; c++) { p0[c] = 0.0f; p1[c] = 0.0f; }

    #pragma unroll
    for (int t = 0; t < 8; t++) {
        int jj = lane + t * 32;
        float wo0 = Wo[jj * 2 + 0];
        float wo1 = Wo[jj * 2 + 1];
        const float* sp = &st[warp * SROW + jj * 8];
        #pragma unroll
        for (int c = 0; c < 8; c++) {
            float sv = sp[c];
            p0[c] = fmaf(sv, wo0, p0[c]);
            p1[c] = fmaf(sv, wo1, p1[c]);
        }
    }
    #pragma unroll
    for (int off = 16; off > 0; off >>= 1) {
        #pragma unroll
        for (int c = 0; c < 8; c++) {
            p0[c] += __shfl_xor_sync(0xffffffffu, p0[c], off);
            p1[c] += __shfl_xor_sync(0xffffffffu, p1[c], off);
        }
    }

    if (lane == 0 && gs < B) {
        float c   = p0[0] + bo[0];
        float Fi  = p1[0] + bo[1];
        float ct  = p0[4];                      // dc/dx3 (TDIM=3)
        float cg0 = p0[1], cg1 = p0[2], cg2 = p0[3];
        float fg0 = p1[1], fg1 = p1[2], fg2 = p1[3];
        float clap = p0[5] + p0[6] + p0[7];     // trace Hc[:3,:3]
        float flap = p1[5] + p1[6] + p1[7];     // trace HFi[:3,:3]
        float jdiv = -clap
                   - (cg0 * fg0 + cg1 * fg1 + cg2 * fg2 + c * flap)
                   + 0.1f * (cg0 + cg1 + cg2);

        out[gs]                   = c;
        out[B + gs]               = ct;
        out[2 * B + gs * 3 + 0]   = cg0;
        out[2 * B + gs * 3 + 1]   = cg1;
        out[2 * B + gs * 3 + 2]   = cg2;
        out[5 * B + gs]           = Fi;
        out[6 * B + gs * 3 + 0]   = fg0;
        out[6 * B + gs * 3 + 1]   = fg1;
        out[6 * B + gs * 3 + 2]   = fg2;
        out[9 * B + gs]           = flap;
        out[10 * B + gs]          = jdiv;
    }
}

extern "C" void kernel_launch(void* const* d_in, const int* in_sizes, int n_in,
                              void* d_out, int out_size)
{
    const float* x  = (const float*)d_in[0];
    const float* W0 = (const float*)d_in[1];
    const float* b0 = (const float*)d_in[2];
    const float* W1 = (const float*)d_in[3];
    const float* b1 = (const float*)d_in[4];
    const float* W2 = (const float*)d_in[5];
    const float* b2 = (const float*)d_in[6];
    const float* W3 = (const float*)d_in[7];
    const float* b3 = (const float*)d_in[8];
    const float* Wo = (const float*)d_in[9];
    const float* bo = (const float*)d_in[10];
    float* out = (float*)d_out;

    const int B = in_sizes[0] / DIN;
    const int smem = (KT * HDIM + SAMP * SROW) * (int)sizeof(float);  // ~96.8 KB

    cudaFuncSetAttribute(mlp_jet_kernel,
                         cudaFuncAttributeMaxDynamicSharedMemorySize, smem);

    dim3 grid((B + SAMP - 1) / SAMP);
    mlp_jet_kernel<<<grid, 256, smem>>>(x, W0, b0, W1, b1, W2, b2, W3, b3,
                                        Wo, bo, out, B);
}

// round 9
// speedup vs baseline: 1.6649x; 1.0001x over previous
#include <cuda_runtime.h>

// GradientLayer: 4->256->256->256->256->2 tanh MLP, forward jet propagation of
// (value, d/dx0..d/dx3, d2/dx0^2..d2/dx2^2) = 8 channels per neuron.
// Register-tiled jet-GEMM: thread (m = sample, n = j-group) owns an
// 8ch x 8j accumulator tile of f32x2 pairs; A-frag (state) and B-frag
// (smem-staged W tile) are reused 8x per load, flipping the bottleneck
// from the smem pipe (95% in R4) to the FFMA2 pipe.

#define HDIM 256
#define SAMP 8
#define DIN  4
#define KT   32                    // k rows staged per W tile
#define SROW 2052                  // state floats per sample: 256*8 + 4 pad (bank spread)

__device__ __forceinline__ unsigned long long ffma2(unsigned long long a,
                                                    unsigned long long b,
                                                    unsigned long long c) {
    unsigned long long d;
    asm("fma.rn.f32x2 %0, %1, %2, %3;" : "=l"(d) : "l"(a), "l"(b), "l"(c));
    return d;
}
__device__ __forceinline__ unsigned long long pack2(float lo, float hi) {
    unsigned long long r;
    asm("mov.b64 %0, {%1, %2};" : "=l"(r) : "f"(lo), "f"(hi));
    return r;
}
__device__ __forceinline__ void unpack2(unsigned long long v, float& a, float& b) {
    asm("mov.b64 {%0, %1}, %2;" : "=f"(a), "=f"(b) : "l"(v));
}

__global__ void __launch_bounds__(256, 2)
mlp_jet_kernel(const float* __restrict__ x,
               const float* __restrict__ W0, const float* __restrict__ b0,
               const float* __restrict__ W1, const float* __restrict__ b1,
               const float* __restrict__ W2, const float* __restrict__ b2,
               const float* __restrict__ W3, const float* __restrict__ b3,
               const float* __restrict__ Wo, const float* __restrict__ bo,
               float* __restrict__ out, int B)
{
    extern __shared__ float smem[];
    float* wsm = smem;                    // KT x 256 staged W tile (32 KB)
    float* st  = smem + KT * HDIM;        // state: SAMP x SROW (~64 KB, padded)
    __shared__ float xs[SAMP * DIN];

    const int tid = threadIdx.x;
    const int m   = tid & 7;              // sample within block
    const int n   = tid >> 3;             // j-group: this thread owns j0..j0+7
    const int j0  = n * 8;
    const int s0  = blockIdx.x * SAMP;

    if (tid < SAMP * DIN) {
        int ss = tid / DIN, kk = tid % DIN;
        int gs = s0 + ss;
        xs[tid] = (gs < B) ? x[gs * DIN + kk] : 0.0f;
    }
    __syncthreads();

    // ---- layer 0: 4 -> 256. Input jets: g_i = e_i, h = 0. ----
    {
        float x0 = xs[m * 4 + 0], x1 = xs[m * 4 + 1];
        float x2 = xs[m * 4 + 2], x3 = xs[m * 4 + 3];
        float4 w0a = *(const float4*)(W0 + 0 * HDIM + j0);
        float4 w0b = *(const float4*)(W0 + 0 * HDIM + j0 + 4);
        float4 w1a = *(const float4*)(W0 + 1 * HDIM + j0);
        float4 w1b = *(const float4*)(W0 + 1 * HDIM + j0 + 4);
        float4 w2a = *(const float4*)(W0 + 2 * HDIM + j0);
        float4 w2b = *(const float4*)(W0 + 2 * HDIM + j0 + 4);
        float4 w3a = *(const float4*)(W0 + 3 * HDIM + j0);
        float4 w3b = *(const float4*)(W0 + 3 * HDIM + j0 + 4);
        float4 ba  = *(const float4*)(b0 + j0);
        float4 bb  = *(const float4*)(b0 + j0 + 4);
        const float* wa0 = &w0a.x; const float* wb0 = &w0b.x;
        const float* wa1 = &w1a.x; const float* wb1 = &w1b.x;
        const float* wa2 = &w2a.x; const float* wb2 = &w2b.x;
        const float* wa3 = &w3a.x; const float* wb3 = &w3b.x;
        const float* bap = &ba.x;  const float* bbp = &bb.x;
        #pragma unroll
        for (int jj = 0; jj < 8; jj++) {
            float c0 = (jj < 4) ? wa0[jj & 3] : wb0[jj & 3];
            float c1 = (jj < 4) ? wa1[jj & 3] : wb1[jj & 3];
            float c2 = (jj < 4) ? wa2[jj & 3] : wb2[jj & 3];
            float c3 = (jj < 4) ? wa3[jj & 3] : wb3[jj & 3];
            float bl = (jj < 4) ? bap[jj & 3] : bbp[jj & 3];
            float u = bl + x0 * c0 + x1 * c1 + x2 * c2 + x3 * c3;
            float v = tanhf(u);
            float d = 1.0f - v * v;
            float mm = -2.0f * v * d;
            float4* p = (float4*)&st[m * SROW + (j0 + jj) * 8];
            p[0] = make_float4(v, d * c0, d * c1, d * c2);
            p[1] = make_float4(d * c3, mm * c0 * c0, mm * c1 * c1, mm * c2 * c2);
        }
    }

    // ---- hidden layers 1..3: 256 -> 256 register-tiled jet GEMM ----
    const float* Wlist[3] = { W1, W2, W3 };
    const float* blist[3] = { b1, b2, b3 };
    #pragma unroll 1
    for (int layer = 0; layer < 3; layer++) {
        const float* __restrict__ Wl = Wlist[layer];

        unsigned long long acc0[8], acc1[8], acc2[8], acc3[8];
        #pragma unroll
        for (int jj = 0; jj < 8; jj++) {
            acc0[jj] = 0ull; acc1[jj] = 0ull; acc2[jj] = 0ull; acc3[jj] = 0ull;
        }

        #pragma unroll 1
        for (int t = 0; t < HDIM / KT; t++) {
            __syncthreads();   // prior tile fully consumed / prior state written
            // stage W rows [t*KT, t*KT+KT) : KT*256 floats, coalesced float4
            {
                const float4* src = (const float4*)(Wl + t * KT * HDIM);
                float4* dst = (float4*)wsm;
                #pragma unroll
                for (int i = 0; i < (KT * HDIM / 4) / 256; i++)
                    dst[tid + i * 256] = src[tid + i * 256];
            }
            __syncthreads();

            const float* abase = st + m * SROW + t * KT * 8;
            #pragma unroll 8
            for (int kk = 0; kk < KT; kk++) {
                const ulonglong2* ap = (const ulonglong2*)(abase + kk * 8);
                ulonglong2 a01 = ap[0];   // (v,g0) | (g1,g2)
                ulonglong2 a23 = ap[1];   // (g3,h0) | (h1,h2)
                const float* wr = wsm + kk * HDIM + j0;
                float4 wlo = *(const float4*)wr;
                float4 whi = *(const float4*)(wr + 4);
                unsigned long long ww[8];
                ww[0] = pack2(wlo.x, wlo.x); ww[1] = pack2(wlo.y, wlo.y);
                ww[2] = pack2(wlo.z, wlo.z); ww[3] = pack2(wlo.w, wlo.w);
                ww[4] = pack2(whi.x, whi.x); ww[5] = pack2(whi.y, whi.y);
                ww[6] = pack2(whi.z, whi.z); ww[7] = pack2(whi.w, whi.w);
                #pragma unroll
                for (int jj = 0; jj < 8; jj++) {
                    acc0[jj] = ffma2(a01.x, ww[jj], acc0[jj]);
                    acc1[jj] = ffma2(a01.y, ww[jj], acc1[jj]);
                    acc2[jj] = ffma2(a23.x, ww[jj], acc2[jj]);
                    acc3[jj] = ffma2(a23.y, ww[jj], acc3[jj]);
                }
            }
        }

        float4 bla = *(const float4*)(blist[layer] + j0);
        float4 blb = *(const float4*)(blist[layer] + j0 + 4);
        const float* blap = &bla.x; const float* blbp = &blb.x;

        __syncthreads();   // all reads of current state done before overwrite

        #pragma unroll
        for (int jj = 0; jj < 8; jj++) {
            float uv, g0, g1, g2, g3, h0, h1, h2;
            unpack2(acc0[jj], uv, g0);
            unpack2(acc1[jj], g1, g2);
            unpack2(acc2[jj], g3, h0);
            unpack2(acc3[jj], h1, h2);
            uv += (jj < 4) ? blap[jj & 3] : blbp[jj & 3];
            float v = tanhf(uv);
            float d = 1.0f - v * v;
            float mm = -2.0f * v * d;
            float4* p = (float4*)&st[m * SROW + (j0 + jj) * 8];
            p[0] = make_float4(v, d * g0, d * g1, d * g2);
            p[1] = make_float4(d * g3,
                               d * h0 + mm * g0 * g0,
                               d * h1 + mm * g1 * g1,
                               d * h2 + mm * g2 * g2);
        }
    }
    __syncthreads();

    // ---- output layer 256 -> 2 + divergence epilogue: one warp per sample ----
    const int warp = tid >> 5;
    const int lane = tid & 31;
    const int gs   = s0 + warp;

    float p0[8], p1[8];
    #pragma unroll
    for (int c = 0; c < 8; c++) { p0[c] = 0.0f; p1[c] = 0.0f; }

    #pragma unroll
    for (int t = 0; t < 8; t++) {
        int jj = lane + t * 32;
        float wo0 = Wo[jj * 2 + 0];
        float wo1 = Wo[jj * 2 + 1];
        const float* sp = &st[warp * SROW + jj * 8];
        #pragma unroll
        for (int c = 0; c < 8; c++) {
            float sv = sp[c];
            p0[c] = fmaf(sv, wo0, p0[c]);
            p1[c] = fmaf(sv, wo1, p1[c]);
        }
    }
    #pragma unroll
    for (int off = 16; off > 0; off >>= 1) {
        #pragma unroll
        for (int c = 0; c < 8; c++) {
            p0[c] += __shfl_xor_sync(0xffffffffu, p0[c], off);
            p1[c] += __shfl_xor_sync(0xffffffffu, p1[c], off);
        }
    }

    if (lane == 0 && gs < B) {
        float c   = p0[0] + bo[0];
        float Fi  = p1[0] + bo[1];
        float ct  = p0[4];                      // dc/dx3 (TDIM=3)
        float cg0 = p0[1], cg1 = p0[2], cg2 = p0[3];
        float fg0 = p1[1], fg1 = p1[2], fg2 = p1[3];
        float clap = p0[5] + p0[6] + p0[7];     // trace Hc[:3,:3]
        float flap = p1[5] + p1[6] + p1[7];     // trace HFi[:3,:3]
        float jdiv = -clap
                   - (cg0 * fg0 + cg1 * fg1 + cg2 * fg2 + c * flap)
                   + 0.1f * (cg0 + cg1 + cg2);

        out[gs]                   = c;
        out[B + gs]               = ct;
        out[2 * B + gs * 3 + 0]   = cg0;
        out[2 * B + gs * 3 + 1]   = cg1;
        out[2 * B + gs * 3 + 2]   = cg2;
        out[5 * B + gs]           = Fi;
        out[6 * B + gs * 3 + 0]   = fg0;
        out[6 * B + gs * 3 + 1]   = fg1;
        out[6 * B + gs * 3 + 2]   = fg2;
        out[9 * B + gs]           = flap;
        out[10 * B + gs]          = jdiv;
    }
}

extern "C" void kernel_launch(void* const* d_in, const int* in_sizes, int n_in,
                              void* d_out, int out_size)
{
    const float* x  = (const float*)d_in[0];
    const float* W0 = (const float*)d_in[1];
    const float* b0 = (const float*)d_in[2];
    const float* W1 = (const float*)d_in[3];
    const float* b1 = (const float*)d_in[4];
    const float* W2 = (const float*)d_in[5];
    const float* b2 = (const float*)d_in[6];
    const float* W3 = (const float*)d_in[7];
    const float* b3 = (const float*)d_in[8];
    const float* Wo = (const float*)d_in[9];
    const float* bo = (const float*)d_in[10];
    float* out = (float*)d_out;

    const int B = in_sizes[0] / DIN;
    const int smem = (KT * HDIM + SAMP * SROW) * (int)sizeof(float);  // ~96.8 KB

    cudaFuncSetAttribute(mlp_jet_kernel,
                         cudaFuncAttributeMaxDynamicSharedMemorySize, smem);

    dim3 grid((B + SAMP - 1) / SAMP);
    mlp_jet_kernel<<<grid, 256, smem>>>(x, W0, b0, W1, b1, W2, b2, W3, b3,
                                        Wo, bo, out, B);
}